// round 1
// baseline (speedup 1.0000x reference)
#include <cuda_runtime.h>

#define TPB 256
#define MAXI 4   // supports V up to 4096 (float4 iters per thread)

// Map float to monotonically orderable unsigned key.
__device__ __forceinline__ unsigned fkey(float f) {
    unsigned u = __float_as_uint(f);
    unsigned mask = (unsigned)((int)u >> 31) | 0x80000000u;
    return u ^ mask;
}

__global__ __launch_bounds__(TPB)
void sampler_kernel(const float* __restrict__ logits,
                    const float* __restrict__ uin,
                    float* __restrict__ out_samp,
                    float* __restrict__ out_probs,
                    int V, int nIter)
{
    __shared__ float s_red[TPB / 32];
    __shared__ int   s_idx[TPB / 32];
    __shared__ float s_bins[16];
    __shared__ float s_b0;

    const int row  = blockIdx.x;
    const int t    = threadIdx.x;
    const int lane = t & 31;
    const int warp = t >> 5;
    const int NV4  = V >> 2;
    const float NEG_INF = __int_as_float(0xff800000);

    const float4* lg4 = reinterpret_cast<const float4*>(logits) + (size_t)row * NV4;
    const float4* u4  = reinterpret_cast<const float4*>(uin)    + (size_t)row * NV4;
    float4*       pr4 = reinterpret_cast<float4*>(out_probs)    + (size_t)row * NV4;

    float x[4 * MAXI];

    // ---- load + temperature scale, track max ----
    float m = NEG_INF;
    #pragma unroll
    for (int k = 0; k < MAXI; k++) {
        if (k >= nIter) break;
        int i4 = k * TPB + t;
        float4 v = (i4 < NV4) ? lg4[i4]
                              : make_float4(NEG_INF, NEG_INF, NEG_INF, NEG_INF);
        x[4*k+0] = v.x / 0.8f;
        x[4*k+1] = v.y / 0.8f;
        x[4*k+2] = v.z / 0.8f;
        x[4*k+3] = v.w / 0.8f;
        m = fmaxf(m, fmaxf(fmaxf(x[4*k+0], x[4*k+1]), fmaxf(x[4*k+2], x[4*k+3])));
    }

    // ---- block max ----
    for (int o = 16; o; o >>= 1) m = fmaxf(m, __shfl_xor_sync(0xffffffffu, m, o));
    if (lane == 0) s_red[warp] = m;
    __syncthreads();
    if (t == 0) {
        float mm = s_red[0];
        #pragma unroll
        for (int i = 1; i < TPB/32; i++) mm = fmaxf(mm, s_red[i]);
        s_b0 = mm;
    }
    __syncthreads();
    m = s_b0;

    // ---- exp + block sum ----
    float e[4 * MAXI];
    float zs = 0.f;
    #pragma unroll
    for (int k = 0; k < MAXI; k++) {
        if (k >= nIter) break;
        #pragma unroll
        for (int c = 0; c < 4; c++) {
            int j = 4*k + c;
            e[j] = expf(x[j] - m);   // exp(-inf) == 0 for padding
            zs += e[j];
        }
    }
    for (int o = 16; o; o >>= 1) zs += __shfl_xor_sync(0xffffffffu, zs, o);
    __syncthreads();              // protect s_red reuse
    if (lane == 0) s_red[warp] = zs;
    __syncthreads();
    if (t == 0) {
        float ss = 0.f;
        #pragma unroll
        for (int i = 0; i < TPB/32; i++) ss += s_red[i];
        s_b0 = ss;
    }
    __syncthreads();
    const float invZ = 1.f / s_b0;

    // ---- keys + normalized mass ----
    unsigned key[4 * MAXI];
    float    p[4 * MAXI];
    #pragma unroll
    for (int k = 0; k < MAXI; k++) {
        if (k >= nIter) break;
        #pragma unroll
        for (int c = 0; c < 4; c++) {
            int j = 4*k + c;
            key[j] = fkey(x[j]);
            p[j]   = e[j] * invZ;
        }
    }

    // ---- weighted radix-select of the top-p threshold key ----
    // Find key k* such that mass(keys > k*) <= 0.95 < mass(keys >= k*).
    // Kept set == {key >= k*}, matching the reference's shifted cumsum rule.
    unsigned hi = 0;
    float G = 0.f;     // mass of keys strictly above the current candidate bin
    for (int pass = 7; pass >= 0; pass--) {
        __syncthreads();
        if (t < 16) s_bins[t] = 0.f;
        __syncthreads();
        const int sh = pass * 4;
        #pragma unroll
        for (int k = 0; k < MAXI; k++) {
            if (k >= nIter) break;
            #pragma unroll
            for (int c = 0; c < 4; c++) {
                int j = 4*k + c;
                unsigned kk = key[j];
                bool cand = (pass == 7) || ((kk >> (sh + 4)) == hi);
                if (cand && p[j] > 0.f)
                    atomicAdd(&s_bins[(kk >> sh) & 15u], p[j]);
            }
        }
        __syncthreads();
        // redundant identical scan on every thread (uniform, no broadcast needed)
        float cum = G;
        int b = -1;
        #pragma unroll
        for (int bi = 15; bi >= 0; bi--) {
            float nb = s_bins[bi];
            if (b < 0) {
                if (cum + nb > 0.95f) b = bi;
                else cum += nb;
            }
        }
        if (b < 0) { b = 0; cum -= s_bins[0]; }  // rounding pathological fallback
        G = cum;
        hi = (hi << 4) | (unsigned)b;
    }
    const unsigned kThr = hi;

    // ---- renormalization mass over kept set ----
    float se = 0.f;
    #pragma unroll
    for (int k = 0; k < MAXI; k++) {
        if (k >= nIter) break;
        #pragma unroll
        for (int c = 0; c < 4; c++) {
            int j = 4*k + c;
            if (key[j] >= kThr) se += e[j];
        }
    }
    for (int o = 16; o; o >>= 1) se += __shfl_xor_sync(0xffffffffu, se, o);
    __syncthreads();
    if (lane == 0) s_red[warp] = se;
    __syncthreads();
    if (t == 0) {
        float ss = 0.f;
        #pragma unroll
        for (int i = 0; i < TPB/32; i++) ss += s_red[i];
        s_b0 = ss;
    }
    __syncthreads();
    const float rinv = 1.f / s_b0;

    // ---- write probs ----
    #pragma unroll
    for (int k = 0; k < MAXI; k++) {
        if (k >= nIter) break;
        int i4 = k * TPB + t;
        if (i4 < NV4) {
            float4 o;
            o.x = (key[4*k+0] >= kThr) ? e[4*k+0] * rinv : 0.f;
            o.y = (key[4*k+1] >= kThr) ? e[4*k+1] * rinv : 0.f;
            o.z = (key[4*k+2] >= kThr) ? e[4*k+2] * rinv : 0.f;
            o.w = (key[4*k+3] >= kThr) ? e[4*k+3] * rinv : 0.f;
            pr4[i4] = o;
        }
    }

    // ---- Gumbel-max argmax over kept set ----
    float best = NEG_INF;
    int   bidx = 0x7fffffff;
    #pragma unroll
    for (int k = 0; k < MAXI; k++) {
        if (k >= nIter) break;
        int i4 = k * TPB + t;
        if (i4 < NV4) {
            float4 uu = u4[i4];
            float uv[4] = {uu.x, uu.y, uu.z, uu.w};
            int base = i4 * 4;
            #pragma unroll
            for (int c = 0; c < 4; c++) {
                int j = 4*k + c;
                if (key[j] >= kThr) {
                    float g = -logf(-logf(uv[c]));
                    float val = x[j] + g;
                    int idx = base + c;
                    if (val > best || (val == best && idx < bidx)) {
                        best = val; bidx = idx;
                    }
                }
            }
        }
    }
    // warp argmax (min index on ties, matching jnp.argmax first-hit)
    for (int o = 16; o; o >>= 1) {
        float v2 = __shfl_xor_sync(0xffffffffu, best, o);
        int   i2 = __shfl_xor_sync(0xffffffffu, bidx, o);
        if (v2 > best || (v2 == best && i2 < bidx)) { best = v2; bidx = i2; }
    }
    __syncthreads();  // protect s_red/s_idx reuse
    if (lane == 0) { s_red[warp] = best; s_idx[warp] = bidx; }
    __syncthreads();
    if (t == 0) {
        float bb = s_red[0]; int bi = s_idx[0];
        #pragma unroll
        for (int i = 1; i < TPB/32; i++) {
            float v2 = s_red[i]; int i2 = s_idx[i];
            if (v2 > bb || (v2 == bb && i2 < bi)) { bb = v2; bi = i2; }
        }
        out_samp[row] = (float)bi;
    }
}

extern "C" void kernel_launch(void* const* d_in, const int* in_sizes, int n_in,
                              void* d_out, int out_size) {
    const float* logits = (const float*)d_in[0];
    const float* u      = (const float*)d_in[1];
    float* out = (float*)d_out;

    // out = [sampled (B) ; probs (B*V)] in float32, B*V == in_sizes[0]
    int total = in_sizes[0];
    int B = out_size - total;
    int V;
    if (B > 0 && total % B == 0) {
        V = total / B;
    } else {
        V = 2048;                // fallback to known shape
        B = total / V;
    }
    int NV4 = V / 4;
    int nIter = (NV4 + TPB - 1) / TPB;

    sampler_kernel<<<B, TPB>>>(logits, u, out, out + B, V, nIter);
}

// round 2
// speedup vs baseline: 2.8286x; 2.8286x over previous
#include <cuda_runtime.h>

#define TPB 256

// Map float to monotonically orderable unsigned key.
__device__ __forceinline__ unsigned fkey(float f) {
    unsigned u = __float_as_uint(f);
    return u ^ ((unsigned)((int)u >> 31) | 0x80000000u);
}

template<int NITER>
__global__ __launch_bounds__(TPB, 4)
void sampler_kernel(const float* __restrict__ logits,
                    const float* __restrict__ uin,
                    float* __restrict__ out_samp,
                    float* __restrict__ out_probs,
                    int NV4)
{
    __shared__ float s_red[TPB / 32];
    __shared__ int   s_idx[TPB / 32];
    __shared__ float s_bins[8][16];   // per-warp privatized histogram
    __shared__ float s_b0;

    const int row  = blockIdx.x;
    const int t    = threadIdx.x;
    const int lane = t & 31;
    const int warp = t >> 5;
    const float NEG_INF = __int_as_float(0xff800000);

    const float4* lg4 = reinterpret_cast<const float4*>(logits) + (size_t)row * NV4;
    const float4* u4  = reinterpret_cast<const float4*>(uin)    + (size_t)row * NV4;
    float4*       pr4 = reinterpret_cast<float4*>(out_probs)    + (size_t)row * NV4;

    float x[4 * NITER];

    // ---- load + temperature scale, track max ----
    float m = NEG_INF;
    #pragma unroll
    for (int k = 0; k < NITER; k++) {
        int i4 = k * TPB + t;
        float4 v = (i4 < NV4) ? __ldcs(&lg4[i4])
                              : make_float4(NEG_INF, NEG_INF, NEG_INF, NEG_INF);
        x[4*k+0] = v.x / 0.8f;
        x[4*k+1] = v.y / 0.8f;
        x[4*k+2] = v.z / 0.8f;
        x[4*k+3] = v.w / 0.8f;
        m = fmaxf(m, fmaxf(fmaxf(x[4*k+0], x[4*k+1]), fmaxf(x[4*k+2], x[4*k+3])));
    }

    // ---- block max ----
    for (int o = 16; o; o >>= 1) m = fmaxf(m, __shfl_xor_sync(0xffffffffu, m, o));
    if (lane == 0) s_red[warp] = m;
    __syncthreads();
    if (t == 0) {
        float mm = s_red[0];
        #pragma unroll
        for (int i = 1; i < TPB/32; i++) mm = fmaxf(mm, s_red[i]);
        s_b0 = mm;
    }
    __syncthreads();
    m = s_b0;

    // ---- exp + block sum (unnormalized mass) ----
    float e[4 * NITER];
    float zs = 0.f;
    #pragma unroll
    for (int j = 0; j < 4 * NITER; j++) {
        e[j] = expf(x[j] - m);       // exp(-inf) == 0 for padding
        zs += e[j];
    }
    for (int o = 16; o; o >>= 1) zs += __shfl_xor_sync(0xffffffffu, zs, o);
    __syncthreads();
    if (lane == 0) s_red[warp] = zs;
    __syncthreads();
    if (t == 0) {
        float ss = 0.f;
        #pragma unroll
        for (int i = 0; i < TPB/32; i++) ss += s_red[i];
        s_b0 = ss;
    }
    __syncthreads();
    const float target = 0.95f * s_b0;   // top-p threshold on unnormalized mass

    // ---- orderable keys ----
    unsigned key[4 * NITER];
    #pragma unroll
    for (int j = 0; j < 4 * NITER; j++) key[j] = fkey(x[j]);

    // ---- weighted radix-select of the top-p threshold key ----
    // Find k* with mass(keys > k*) <= target < mass(keys >= k*);
    // kept set == {key >= k*}, matching the reference's shifted-cumsum rule.
    unsigned hi = 0;
    float G = 0.f;          // mass strictly above the current candidate region
    float keptMass = 0.f;
    #pragma unroll 1
    for (int pass = 7; pass >= 0; pass--) {
        __syncthreads();                      // protect prior-pass scan reads
        if (t < 128) (&s_bins[0][0])[t] = 0.f;
        __syncthreads();
        const int sh = pass * 4;
        #pragma unroll
        for (int j = 0; j < 4 * NITER; j++) {
            unsigned kk = key[j];
            bool cand = (pass == 7) || ((kk >> (sh + 4)) == hi);
            if (cand && e[j] > 0.f)
                atomicAdd(&s_bins[warp][(kk >> sh) & 15u], e[j]);
        }
        __syncthreads();
        if (t < 16) {                         // fold warp copies into row 0
            float s = s_bins[0][t];
            #pragma unroll
            for (int w = 1; w < 8; w++) s += s_bins[w][t];
            s_bins[0][t] = s;
        }
        __syncthreads();
        // redundant identical scan on every thread (uniform result)
        float cum = G;
        int b = -1;
        #pragma unroll
        for (int bi = 15; bi >= 0; bi--) {
            float nb = s_bins[0][bi];
            if (b < 0) {
                if (cum + nb > target) b = bi;
                else cum += nb;
            }
        }
        if (b < 0) { b = 0; cum -= s_bins[0][0]; }   // rounding fallback
        G = cum;
        hi = (hi << 4) | (unsigned)b;
        if (pass == 0) keptMass = cum + s_bins[0][b];
    }
    const unsigned kThr = hi;
    const float rinv = 1.f / keptMass;

    // ---- write probs ----
    #pragma unroll
    for (int k = 0; k < NITER; k++) {
        int i4 = k * TPB + t;
        if (i4 < NV4) {
            float4 o;
            o.x = (key[4*k+0] >= kThr) ? e[4*k+0] * rinv : 0.f;
            o.y = (key[4*k+1] >= kThr) ? e[4*k+1] * rinv : 0.f;
            o.z = (key[4*k+2] >= kThr) ? e[4*k+2] * rinv : 0.f;
            o.w = (key[4*k+3] >= kThr) ? e[4*k+3] * rinv : 0.f;
            pr4[i4] = o;
        }
    }

    // ---- Gumbel-max argmax over kept set ----
    float best = NEG_INF;
    int   bidx = 0x7fffffff;
    #pragma unroll
    for (int k = 0; k < NITER; k++) {
        int i4 = k * TPB + t;
        if (i4 < NV4) {
            float4 uu = __ldcs(&u4[i4]);
            float uv[4] = {uu.x, uu.y, uu.z, uu.w};
            int base = i4 * 4;
            #pragma unroll
            for (int c = 0; c < 4; c++) {
                int j = 4*k + c;
                if (key[j] >= kThr) {
                    float g = -logf(-logf(uv[c]));
                    float val = x[j] + g;
                    int idx = base + c;
                    if (val > best || (val == best && idx < bidx)) {
                        best = val; bidx = idx;
                    }
                }
            }
        }
    }
    for (int o = 16; o; o >>= 1) {
        float v2 = __shfl_xor_sync(0xffffffffu, best, o);
        int   i2 = __shfl_xor_sync(0xffffffffu, bidx, o);
        if (v2 > best || (v2 == best && i2 < bidx)) { best = v2; bidx = i2; }
    }
    __syncthreads();   // s_red/s_idx reuse
    if (lane == 0) { s_red[warp] = best; s_idx[warp] = bidx; }
    __syncthreads();
    if (t == 0) {
        float bb = s_red[0]; int bi = s_idx[0];
        #pragma unroll
        for (int i = 1; i < TPB/32; i++) {
            float v2 = s_red[i]; int i2 = s_idx[i];
            if (v2 > bb || (v2 == bb && i2 < bi)) { bb = v2; bi = i2; }
        }
        out_samp[row] = (float)bi;
    }
}

extern "C" void kernel_launch(void* const* d_in, const int* in_sizes, int n_in,
                              void* d_out, int out_size) {
    const float* logits = (const float*)d_in[0];
    const float* u      = (const float*)d_in[1];
    float* out = (float*)d_out;

    // out = [sampled (B) ; probs (B*V)] float32, B*V == in_sizes[0]
    int total = in_sizes[0];
    int B = out_size - total;
    int V;
    if (B > 0 && total % B == 0) {
        V = total / B;
    } else {
        V = 2048;
        B = total / V;
    }
    int NV4 = V / 4;
    int nIter = (NV4 + TPB - 1) / TPB;

    if (nIter <= 1)      sampler_kernel<1><<<B, TPB>>>(logits, u, out, out + B, NV4);
    else if (nIter <= 2) sampler_kernel<2><<<B, TPB>>>(logits, u, out, out + B, NV4);
    else if (nIter <= 4) sampler_kernel<4><<<B, TPB>>>(logits, u, out, out + B, NV4);
    else                 sampler_kernel<8><<<B, TPB>>>(logits, u, out, out + B, NV4);
}

// round 6
// speedup vs baseline: 4.4244x; 1.5642x over previous
#include <cuda_runtime.h>

#define TPB 256

// Bijective, order-preserving float -> uint key (and inverse).
__device__ __forceinline__ unsigned fkey(float f) {
    unsigned u = __float_as_uint(f);
    return u ^ ((unsigned)((int)u >> 31) | 0x80000000u);
}
__device__ __forceinline__ float unkey(unsigned k) {
    unsigned u = (k & 0x80000000u) ? (k ^ 0x80000000u) : ~k;
    return __uint_as_float(u);
}

template<int NITER>
__global__ __launch_bounds__(TPB, 4)
void sampler_kernel(const float* __restrict__ logits,
                    const float* __restrict__ uin,
                    float* __restrict__ out_samp,
                    float* __restrict__ out_probs,
                    int NV4)
{
    __shared__ float s_binsW[8][256];   // per-warp privatized histogram
    __shared__ float s_red[8];
    __shared__ int   s_wi[8];
    __shared__ float s_bc;
    __shared__ int   s_flag, s_fb, s_digit;
    __shared__ float s_G2, s_GB;

    const int row  = blockIdx.x;
    const int t    = threadIdx.x;
    const int lane = t & 31;
    const int warp = t >> 5;
    const float NEG_INF = __int_as_float(0xff800000);

    const float4* lg4 = reinterpret_cast<const float4*>(logits) + (size_t)row * NV4;
    const float4* u4  = reinterpret_cast<const float4*>(uin)    + (size_t)row * NV4;
    float4*       pr4 = reinterpret_cast<float4*>(out_probs)    + (size_t)row * NV4;

    // ---- load + temperature scale (x = logit / 0.8, matches reference) ----
    float x[4 * NITER];
    float m = NEG_INF;
    #pragma unroll
    for (int k = 0; k < NITER; k++) {
        int i4 = k * TPB + t;
        float4 v = (i4 < NV4) ? __ldcs(&lg4[i4])
                              : make_float4(NEG_INF, NEG_INF, NEG_INF, NEG_INF);
        x[4*k+0] = v.x / 0.8f;
        x[4*k+1] = v.y / 0.8f;
        x[4*k+2] = v.z / 0.8f;
        x[4*k+3] = v.w / 0.8f;
        m = fmaxf(m, fmaxf(fmaxf(x[4*k+0], x[4*k+1]), fmaxf(x[4*k+2], x[4*k+3])));
    }

    // ---- block max ----
    for (int o = 16; o; o >>= 1) m = fmaxf(m, __shfl_xor_sync(0xffffffffu, m, o));
    if (lane == 0) s_red[warp] = m;
    __syncthreads();
    if (t == 0) {
        float mm = s_red[0];
        #pragma unroll
        for (int i = 1; i < 8; i++) mm = fmaxf(mm, s_red[i]);
        s_bc = mm;
    }
    __syncthreads();
    m = s_bc;

    // ---- e = exp(x - m) [PRECISE: membership noise must stay ~1e-7]; Z ----
    float e[4 * NITER];
    float zs = 0.f;
    #pragma unroll
    for (int j = 0; j < 4 * NITER; j++) {
        e[j] = expf(x[j] - m);         // 0 for -inf padding
        zs += e[j];
    }
    for (int o = 16; o; o >>= 1) zs += __shfl_xor_sync(0xffffffffu, zs, o);
    __syncthreads();                   // protect s_red reuse
    if (lane == 0) s_red[warp] = zs;
    __syncthreads();
    if (t == 0) {
        float ss = 0.f;
        #pragma unroll
        for (int i = 0; i < 8; i++) ss += s_red[i];
        s_bc = ss;
    }
    __syncthreads();
    const float Z = s_bc;
    const float target = 0.95f * Z;

    // ---- exact radix select on fkey(x), 8-bit digits, MSB first ----
    // Invariant: mass{key > kThr} <= target < mass{key >= kThr}; keep {key >= kThr}.
    unsigned hi = 0;
    float G = 0.f;
    float keptMass = Z;
    #pragma unroll
    for (int pass = 3; pass >= 0; pass--) {
        // barrier: previous pass's s_digit/s_G2/s_GB reads completed by ALL
        // threads before re-initialization below (race fix vs R5)
        __syncthreads();
        float4 z4 = make_float4(0.f, 0.f, 0.f, 0.f);
        float4* b4 = reinterpret_cast<float4*>(&s_binsW[0][0]);
        b4[t] = z4; b4[t + TPB] = z4;
        if (t == 0) { s_flag = 0; s_fb = -1; s_digit = 0; s_G2 = 0.f; s_GB = 0.f; }
        __syncthreads();

        const int sh = pass * 8;
        #pragma unroll
        for (int j = 0; j < 4 * NITER; j++) {
            unsigned kk = fkey(x[j]);
            bool cand = (pass == 3) ? true : ((kk >> (sh + 8)) == hi);
            if (cand)
                atomicAdd(&s_binsW[warp][(kk >> sh) & 255u], e[j]);
        }
        __syncthreads();

        // thread t owns digit dg = 255 - t (descending digit order)
        const int dg = 255 - t;
        float v = 0.f;
        #pragma unroll
        for (int w = 0; w < 8; w++) v += s_binsW[w][dg];

        // block inclusive scan in descending-digit order
        float iv = v;
        #pragma unroll
        for (int o = 1; o < 32; o <<= 1) {
            float n = __shfl_up_sync(0xffffffffu, iv, o);
            if (lane >= o) iv += n;
        }
        if (lane == 31) s_red[warp] = iv;
        __syncthreads();
        float woff = 0.f;
        #pragma unroll
        for (int w = 0; w < 8; w++) if (w < warp) woff += s_red[w];
        const float incl = woff + iv;
        const float up = __shfl_up_sync(0xffffffffu, incl, 1);
        const float prev = (lane == 0) ? woff : up;

        const float tgt = target - G;
        if (incl > tgt && prev <= tgt) {        // unique crossing thread
            s_digit = dg; s_G2 = prev; s_GB = prev + v; s_flag = 1;
        }
        __syncthreads();
        if (s_flag == 0 && v > 0.f) atomicMax(&s_fb, t);  // fallback: smallest
        __syncthreads();                                   // nonzero digit
        if (s_flag == 0 && t == s_fb) {
            s_digit = dg; s_G2 = prev; s_GB = prev + v;
        }
        __syncthreads();

        if (pass == 0) keptMass = G + s_GB;
        G  = G + s_G2;
        hi = (hi << 8) | (unsigned)s_digit;
    }
    const float xThr = unkey(hi);               // kept <=> x >= xThr
    const float rinv = 1.0f / fmaxf(keptMass, 1e-30f);

    // ---- write probs ----
    #pragma unroll
    for (int k = 0; k < NITER; k++) {
        int i4 = k * TPB + t;
        if (i4 < NV4) {
            float4 o;
            o.x = (x[4*k+0] >= xThr) ? e[4*k+0] * rinv : 0.f;
            o.y = (x[4*k+1] >= xThr) ? e[4*k+1] * rinv : 0.f;
            o.z = (x[4*k+2] >= xThr) ? e[4*k+2] * rinv : 0.f;
            o.w = (x[4*k+3] >= xThr) ? e[4*k+3] * rinv : 0.f;
            __stcs(&pr4[i4], o);
        }
    }

    // ---- Gumbel-max argmax over kept set (u loaded only where needed) ----
    float best = NEG_INF;
    int   bidx = 0x7fffffff;
    #pragma unroll
    for (int k = 0; k < NITER; k++) {
        int i4 = k * TPB + t;
        if (i4 < NV4) {
            bool k0 = (x[4*k+0] >= xThr);
            bool k1 = (x[4*k+1] >= xThr);
            bool k2 = (x[4*k+2] >= xThr);
            bool k3 = (x[4*k+3] >= xThr);
            if (k0 | k1 | k2 | k3) {
                float4 uu = __ldcs(&u4[i4]);
                float uv[4] = {uu.x, uu.y, uu.z, uu.w};
                bool kk[4] = {k0, k1, k2, k3};
                int base = i4 * 4;
                #pragma unroll
                for (int ci = 0; ci < 4; ci++) {
                    if (kk[ci]) {
                        float g = -logf(-logf(uv[ci]));   // precise, kept-only
                        float val = x[4*k+ci] + g;        // reference order
                        int idx = base + ci;
                        if (val > best || (val == best && idx < bidx)) {
                            best = val; bidx = idx;
                        }
                    }
                }
            }
        }
    }
    for (int o = 16; o; o >>= 1) {
        float v2 = __shfl_xor_sync(0xffffffffu, best, o);
        int   i2 = __shfl_xor_sync(0xffffffffu, bidx, o);
        if (v2 > best || (v2 == best && i2 < bidx)) { best = v2; bidx = i2; }
    }
    __syncthreads();
    if (lane == 0) { s_red[warp] = best; s_wi[warp] = bidx; }
    __syncthreads();
    if (t == 0) {
        float bb = s_red[0]; int bi = s_wi[0];
        #pragma unroll
        for (int i = 1; i < 8; i++) {
            float v2 = s_red[i]; int i2 = s_wi[i];
            if (v2 > bb || (v2 == bb && i2 < bi)) { bb = v2; bi = i2; }
        }
        out_samp[row] = (float)bi;
    }
}

extern "C" void kernel_launch(void* const* d_in, const int* in_sizes, int n_in,
                              void* d_out, int out_size) {
    const float* logits = (const float*)d_in[0];
    const float* u      = (const float*)d_in[1];
    float* out = (float*)d_out;

    // out = [sampled (B) ; probs (B*V)] float32, B*V == in_sizes[0]
    int total = in_sizes[0];
    int B = out_size - total;
    int V;
    if (B > 0 && total % B == 0) {
        V = total / B;
    } else {
        V = 2048;
        B = total / V;
    }
    int NV4 = V / 4;
    int nIter = (NV4 + TPB - 1) / TPB;

    if (nIter <= 1)      sampler_kernel<1><<<B, TPB>>>(logits, u, out, out + B, NV4);
    else if (nIter <= 2) sampler_kernel<2><<<B, TPB>>>(logits, u, out, out + B, NV4);
    else if (nIter <= 4) sampler_kernel<4><<<B, TPB>>>(logits, u, out, out + B, NV4);
    else                 sampler_kernel<8><<<B, TPB>>>(logits, u, out, out + B, NV4);
}

// round 7
// speedup vs baseline: 6.3222x; 1.4289x over previous
#include <cuda_runtime.h>

#define TPB 256
#define CAP 1024   // candidate capacity (shared pool = 8 KB)

// Bijective, order-preserving float -> uint key (and inverse) — fallback path.
__device__ __forceinline__ unsigned fkey(float f) {
    unsigned u = __float_as_uint(f);
    return u ^ ((unsigned)((int)u >> 31) | 0x80000000u);
}
__device__ __forceinline__ float unkey(unsigned k) {
    unsigned u = (k & 0x80000000u) ? (k ^ 0x80000000u) : ~k;
    return __uint_as_float(u);
}

template<int NITER>
__global__ __launch_bounds__(TPB, 4)
void sampler_kernel(const float* __restrict__ logits,
                    const float* __restrict__ uin,
                    float* __restrict__ out_samp,
                    float* __restrict__ out_probs,
                    int NV4)
{
    __shared__ float s_pool[2048];      // float2 cand[1024] | float bins[8][256]
    __shared__ float s_red[8];
    __shared__ float s_rm[8];
    __shared__ int   s_wi[8];
    __shared__ float s_bc;
    __shared__ int   s_cnt;
    __shared__ int   s_flag, s_fb, s_digit;
    __shared__ float s_G2, s_GB;
    __shared__ float s_fx, s_fm;

    const int row  = blockIdx.x;
    const int t    = threadIdx.x;
    const int lane = t & 31;
    const int warp = t >> 5;
    const float NEG_INF = __int_as_float(0xff800000);

    const float4* lg4 = reinterpret_cast<const float4*>(logits) + (size_t)row * NV4;
    const float4* u4  = reinterpret_cast<const float4*>(uin)    + (size_t)row * NV4;
    float4*       pr4 = reinterpret_cast<float4*>(out_probs)    + (size_t)row * NV4;

    // ---- load + temperature scale (x = logit / 0.8, matches reference) ----
    float x[4 * NITER];
    float m = NEG_INF;
    #pragma unroll
    for (int k = 0; k < NITER; k++) {
        int i4 = k * TPB + t;
        float4 v = (i4 < NV4) ? __ldcs(&lg4[i4])
                              : make_float4(NEG_INF, NEG_INF, NEG_INF, NEG_INF);
        x[4*k+0] = v.x / 0.8f;
        x[4*k+1] = v.y / 0.8f;
        x[4*k+2] = v.z / 0.8f;
        x[4*k+3] = v.w / 0.8f;
        m = fmaxf(m, fmaxf(fmaxf(x[4*k+0], x[4*k+1]), fmaxf(x[4*k+2], x[4*k+3])));
    }

    // ---- block max ----
    for (int o = 16; o; o >>= 1) m = fmaxf(m, __shfl_xor_sync(0xffffffffu, m, o));
    if (lane == 0) s_red[warp] = m;
    __syncthreads();
    if (t == 0) {
        float mm = s_red[0];
        #pragma unroll
        for (int i = 1; i < 8; i++) mm = fmaxf(mm, s_red[i]);
        s_bc = mm;
    }
    __syncthreads();
    m = s_bc;

    // ---- e = exp(x - m) [precise]; Z ----
    float e[4 * NITER];
    float zs = 0.f;
    #pragma unroll
    for (int j = 0; j < 4 * NITER; j++) {
        e[j] = expf(x[j] - m);
        zs += e[j];
    }
    for (int o = 16; o; o >>= 1) zs += __shfl_xor_sync(0xffffffffu, zs, o);
    __syncthreads();
    if (lane == 0) s_red[warp] = zs;
    __syncthreads();
    if (t == 0) {
        float ss = 0.f;
        #pragma unroll
        for (int i = 0; i < 8; i++) ss += s_red[i];
        s_bc = ss;
        s_cnt = 0;
    }
    __syncthreads();
    const float Z = s_bc;
    const float target = 0.95f * Z;
    const int   V = NV4 * 4;

    // ---- candidate prune: x_thr >= m - ln(20V/Z)  (proven top-p bound) ----
    const float cutoff = m - __logf(20.0f * (float)V / Z) - 0.02f;

    // ballot-aggregated gather of (x, e) candidate pairs
    float2* cand = reinterpret_cast<float2*>(s_pool);
    #pragma unroll
    for (int j = 0; j < 4 * NITER; j++) {
        bool pred = (x[j] >= cutoff);
        unsigned bal = __ballot_sync(0xffffffffu, pred);
        if (bal) {
            int ldr = __ffs(bal) - 1;
            int base = 0;
            if (lane == ldr) base = atomicAdd(&s_cnt, __popc(bal));
            base = __shfl_sync(0xffffffffu, base, ldr);
            if (pred) {
                int p = base + __popc(bal & ((1u << lane) - 1u));
                if (p < CAP) cand[p] = make_float2(x[j], e[j]);
            }
        }
    }
    __syncthreads();
    const int C = s_cnt;

    float xThr, keptMass;

    if (C <= CAP) {
        // ---- exact all-pairs threshold among candidates ----
        // xThr = min{xi : mass{x > xi} <= target}; keptMass = above + eq.
        float bx = 3.4e38f, bm = 0.f;
        for (int i = t; i < C; i += TPB) {
            const float xi = cand[i].x;
            float above = 0.f, eq = 0.f;
            #pragma unroll 4
            for (int j = 0; j < C; j++) {
                float2 cj = cand[j];             // broadcast LDS.64
                if (cj.x > xi) above += cj.y;
                else if (cj.x == xi) eq += cj.y;
            }
            if (above <= target && xi < bx) { bx = xi; bm = above + eq; }
        }
        // block min-by-bx reduction with payload bm
        for (int o = 16; o; o >>= 1) {
            float ox = __shfl_xor_sync(0xffffffffu, bx, o);
            float om = __shfl_xor_sync(0xffffffffu, bm, o);
            if (ox < bx) { bx = ox; bm = om; }
        }
        __syncthreads();                         // s_red reuse
        if (lane == 0) { s_red[warp] = bx; s_rm[warp] = bm; }
        __syncthreads();
        if (t == 0) {
            float fx = s_red[0], fm = s_rm[0];
            #pragma unroll
            for (int i = 1; i < 8; i++)
                if (s_red[i] < fx) { fx = s_red[i]; fm = s_rm[i]; }
            s_fx = fx; s_fm = fm;
        }
        __syncthreads();
        xThr = s_fx; keptMass = s_fm;
    } else {
        // ---- fallback: exact radix select on fkey(x) (R6-proven path) ----
        float (*s_binsW)[256] = reinterpret_cast<float (*)[256]>(s_pool);
        unsigned hi = 0;
        float G = 0.f;
        float km = Z;
        #pragma unroll 1
        for (int pass = 3; pass >= 0; pass--) {
            __syncthreads();
            float4 z4 = make_float4(0.f, 0.f, 0.f, 0.f);
            float4* b4 = reinterpret_cast<float4*>(&s_binsW[0][0]);
            b4[t] = z4; b4[t + TPB] = z4;
            if (t == 0) { s_flag = 0; s_fb = -1; s_digit = 0; s_G2 = 0.f; s_GB = 0.f; }
            __syncthreads();

            const int sh = pass * 8;
            #pragma unroll
            for (int j = 0; j < 4 * NITER; j++) {
                unsigned kk = fkey(x[j]);
                bool cnd = (pass == 3) ? true : ((kk >> (sh + 8)) == hi);
                if (cnd)
                    atomicAdd(&s_binsW[warp][(kk >> sh) & 255u], e[j]);
            }
            __syncthreads();

            const int dg = 255 - t;
            float v = 0.f;
            #pragma unroll
            for (int w = 0; w < 8; w++) v += s_binsW[w][dg];

            float iv = v;
            #pragma unroll
            for (int o = 1; o < 32; o <<= 1) {
                float n = __shfl_up_sync(0xffffffffu, iv, o);
                if (lane >= o) iv += n;
            }
            if (lane == 31) s_red[warp] = iv;
            __syncthreads();
            float woff = 0.f;
            #pragma unroll
            for (int w = 0; w < 8; w++) if (w < warp) woff += s_red[w];
            const float incl = woff + iv;
            const float up = __shfl_up_sync(0xffffffffu, incl, 1);
            const float prev = (lane == 0) ? woff : up;

            const float tgt = target - G;
            if (incl > tgt && prev <= tgt) {
                s_digit = dg; s_G2 = prev; s_GB = prev + v; s_flag = 1;
            }
            __syncthreads();
            if (s_flag == 0 && v > 0.f) atomicMax(&s_fb, t);
            __syncthreads();
            if (s_flag == 0 && t == s_fb) {
                s_digit = dg; s_G2 = prev; s_GB = prev + v;
            }
            __syncthreads();

            if (pass == 0) km = G + s_GB;
            G  = G + s_G2;
            hi = (hi << 8) | (unsigned)s_digit;
        }
        xThr = unkey(hi);
        keptMass = km;
    }

    const float rinv = 1.0f / fmaxf(keptMass, 1e-30f);

    // ---- write probs (kept: x >= xThr) ----
    #pragma unroll
    for (int k = 0; k < NITER; k++) {
        int i4 = k * TPB + t;
        if (i4 < NV4) {
            float4 o;
            o.x = (x[4*k+0] >= xThr) ? e[4*k+0] * rinv : 0.f;
            o.y = (x[4*k+1] >= xThr) ? e[4*k+1] * rinv : 0.f;
            o.z = (x[4*k+2] >= xThr) ? e[4*k+2] * rinv : 0.f;
            o.w = (x[4*k+3] >= xThr) ? e[4*k+3] * rinv : 0.f;
            __stcs(&pr4[i4], o);
        }
    }

    // ---- Gumbel-max argmax over kept set (u loaded only where needed) ----
    float best = NEG_INF;
    int   bidx = 0x7fffffff;
    #pragma unroll
    for (int k = 0; k < NITER; k++) {
        int i4 = k * TPB + t;
        if (i4 < NV4) {
            bool k0 = (x[4*k+0] >= xThr);
            bool k1 = (x[4*k+1] >= xThr);
            bool k2 = (x[4*k+2] >= xThr);
            bool k3 = (x[4*k+3] >= xThr);
            if (k0 | k1 | k2 | k3) {
                float4 uu = __ldcs(&u4[i4]);
                float uv[4] = {uu.x, uu.y, uu.z, uu.w};
                bool kk[4] = {k0, k1, k2, k3};
                int base = i4 * 4;
                #pragma unroll
                for (int ci = 0; ci < 4; ci++) {
                    if (kk[ci]) {
                        float g = -logf(-logf(uv[ci]));   // precise, kept-only
                        float val = x[4*k+ci] + g;
                        int idx = base + ci;
                        if (val > best || (val == best && idx < bidx)) {
                            best = val; bidx = idx;
                        }
                    }
                }
            }
        }
    }
    for (int o = 16; o; o >>= 1) {
        float v2 = __shfl_xor_sync(0xffffffffu, best, o);
        int   i2 = __shfl_xor_sync(0xffffffffu, bidx, o);
        if (v2 > best || (v2 == best && i2 < bidx)) { best = v2; bidx = i2; }
    }
    __syncthreads();
    if (lane == 0) { s_red[warp] = best; s_wi[warp] = bidx; }
    __syncthreads();
    if (t == 0) {
        float bb = s_red[0]; int bi = s_wi[0];
        #pragma unroll
        for (int i = 1; i < 8; i++) {
            float v2 = s_red[i]; int i2 = s_wi[i];
            if (v2 > bb || (v2 == bb && i2 < bi)) { bb = v2; bi = i2; }
        }
        out_samp[row] = (float)bi;
    }
}

extern "C" void kernel_launch(void* const* d_in, const int* in_sizes, int n_in,
                              void* d_out, int out_size) {
    const float* logits = (const float*)d_in[0];
    const float* u      = (const float*)d_in[1];
    float* out = (float*)d_out;

    int total = in_sizes[0];
    int B = out_size - total;
    int V;
    if (B > 0 && total % B == 0) {
        V = total / B;
    } else {
        V = 2048;
        B = total / V;
    }
    int NV4 = V / 4;
    int nIter = (NV4 + TPB - 1) / TPB;

    if (nIter <= 1)      sampler_kernel<1><<<B, TPB>>>(logits, u, out, out + B, NV4);
    else if (nIter <= 2) sampler_kernel<2><<<B, TPB>>>(logits, u, out, out + B, NV4);
    else if (nIter <= 4) sampler_kernel<4><<<B, TPB>>>(logits, u, out, out + B, NV4);
    else                 sampler_kernel<8><<<B, TPB>>>(logits, u, out, out + B, NV4);
}

// round 8
// speedup vs baseline: 8.7508x; 1.3842x over previous
#include <cuda_runtime.h>

#define TPB 256

// Bijective, order-preserving float -> uint key (and inverse) — fallback path.
__device__ __forceinline__ unsigned fkey(float f) {
    unsigned u = __float_as_uint(f);
    return u ^ ((unsigned)((int)u >> 31) | 0x80000000u);
}
__device__ __forceinline__ float unkey(unsigned k) {
    unsigned u = (k & 0x80000000u) ? (k ^ 0x80000000u) : ~k;
    return __uint_as_float(u);
}

template<int NITER>
__global__ __launch_bounds__(TPB, 4)
void sampler_kernel(const float* __restrict__ logits,
                    const float* __restrict__ uin,
                    float* __restrict__ out_samp,
                    float* __restrict__ out_probs,
                    int NV4)
{
    // s_pool layout (common path): hist = s_pool[0..255]; cand2 = (float2*)(s_pool+512), cap 256
    // fallback path: 8x256 per-warp radix bins
    __shared__ float s_pool[2048];
    __shared__ float s_red[8];
    __shared__ float s_rm[8];
    __shared__ int   s_wi[8];
    __shared__ float s_bc;
    __shared__ int   s_cnt, s_flag, s_fb, s_digit;
    __shared__ float s_G2, s_GB;
    __shared__ float s_fx, s_fm;

    const int row  = blockIdx.x;
    const int t    = threadIdx.x;
    const int lane = t & 31;
    const int warp = t >> 5;
    const float NEG_INF = __int_as_float(0xff800000);

    const float4* lg4 = reinterpret_cast<const float4*>(logits) + (size_t)row * NV4;
    const float4* u4  = reinterpret_cast<const float4*>(uin)    + (size_t)row * NV4;
    float4*       pr4 = reinterpret_cast<float4*>(out_probs)    + (size_t)row * NV4;

    // ---- load + temperature scale (x = logit / 0.8, matches reference) ----
    float x[4 * NITER];
    float m = NEG_INF;
    #pragma unroll
    for (int k = 0; k < NITER; k++) {
        int i4 = k * TPB + t;
        float4 v = (i4 < NV4) ? __ldcs(&lg4[i4])
                              : make_float4(NEG_INF, NEG_INF, NEG_INF, NEG_INF);
        x[4*k+0] = v.x / 0.8f;
        x[4*k+1] = v.y / 0.8f;
        x[4*k+2] = v.z / 0.8f;
        x[4*k+3] = v.w / 0.8f;
        m = fmaxf(m, fmaxf(fmaxf(x[4*k+0], x[4*k+1]), fmaxf(x[4*k+2], x[4*k+3])));
    }

    // ---- block max ----
    for (int o = 16; o; o >>= 1) m = fmaxf(m, __shfl_xor_sync(0xffffffffu, m, o));
    if (lane == 0) s_red[warp] = m;
    __syncthreads();
    if (t == 0) {
        float mm = s_red[0];
        #pragma unroll
        for (int i = 1; i < 8; i++) mm = fmaxf(mm, s_red[i]);
        s_bc = mm;
    }
    __syncthreads();
    m = s_bc;

    // ---- e = exp(x - m) [precise]; Z (merged with hist zero + flag init) ----
    float e[4 * NITER];
    float zs = 0.f;
    #pragma unroll
    for (int j = 0; j < 4 * NITER; j++) {
        e[j] = expf(x[j] - m);
        zs += e[j];
    }
    for (int o = 16; o; o >>= 1) zs += __shfl_xor_sync(0xffffffffu, zs, o);
    if (lane == 0) s_red[warp] = zs;
    s_pool[t] = 0.f;                              // zero histogram
    if (t == 0) { s_flag = 0; s_fb = -1; s_cnt = 0; }
    __syncthreads();
    if (t == 0) {
        float ss = 0.f;
        #pragma unroll
        for (int i = 0; i < 8; i++) ss += s_red[i];
        s_bc = ss;
    }
    __syncthreads();
    const float Z = s_bc;
    const float target = 0.95f * Z;
    const int   V = NV4 * 4;

    // ---- candidate prune: x_thr >= m - ln(20V/Z) (proven); bin quantization ----
    const float W = __logf(20.0f * (float)V / Z) + 0.02f;   // = m - cutoff, in [3, ~11]
    const float cutoff = m - W;
    const float bsc = 256.0f / W;

    // ---- 256-bin histogram of candidate masses (linear in x) ----
    float* hist = s_pool;
    #pragma unroll
    for (int j = 0; j < 4 * NITER; j++) {
        if (x[j] >= cutoff) {
            int b = (int)((x[j] - cutoff) * bsc);
            b = (b > 255) ? 255 : b;
            atomicAdd(&hist[b], e[j]);
        }
    }
    __syncthreads();

    // ---- descending scan: find crossing bin b* (mass{bin>=b*}>target>=mass{bin>b*}) ----
    const int dg = 255 - t;
    const float v = hist[dg];
    float iv = v;
    #pragma unroll
    for (int o = 1; o < 32; o <<= 1) {
        float n = __shfl_up_sync(0xffffffffu, iv, o);
        if (lane >= o) iv += n;
    }
    if (lane == 31) s_red[warp] = iv;
    __syncthreads();
    float woff = 0.f;
    #pragma unroll
    for (int w = 0; w < 8; w++) if (w < warp) woff += s_red[w];
    const float incl = woff + iv;
    const float up = __shfl_up_sync(0xffffffffu, incl, 1);
    const float prev = (lane == 0) ? woff : up;

    if (incl > target && prev <= target) {        // unique crossing thread
        s_digit = dg; s_G2 = prev; s_flag = 1;
    }
    __syncthreads();
    if (s_flag == 0) {                            // FP-noise fallback (never hit)
        if (v > 0.f) atomicMax(&s_fb, t);
        __syncthreads();
        if (t == s_fb) { s_digit = dg; s_G2 = prev; }
        __syncthreads();
    }
    const int   bstar = s_digit;
    const float Ab    = s_G2;                     // exact mass of bins above b*

    // ---- gather bin-b* candidates (tiny set) from registers ----
    float2* cand2 = reinterpret_cast<float2*>(s_pool + 512);
    #pragma unroll
    for (int j = 0; j < 4 * NITER; j++) {
        bool pred = false;
        if (x[j] >= cutoff) {
            int b = (int)((x[j] - cutoff) * bsc);
            b = (b > 255) ? 255 : b;
            pred = (b == bstar);
        }
        unsigned bal = __ballot_sync(0xffffffffu, pred);
        if (bal) {
            int ldr = __ffs(bal) - 1;
            int base = 0;
            if (lane == ldr) base = atomicAdd(&s_cnt, __popc(bal));
            base = __shfl_sync(0xffffffffu, base, ldr);
            if (pred) {
                int p = base + __popc(bal & ((1u << lane) - 1u));
                if (p < 256) cand2[p] = make_float2(x[j], e[j]);
            }
        }
    }
    __syncthreads();
    const int C2 = s_cnt;

    float xThr, keptMass;

    if (C2 <= 256) {
        // ---- exact all-pairs threshold within bin b* ----
        // xThr = min{xi in b* : Ab + mass{x > xi within b*} <= target}
        float bx = 3.4e38f, bm = 0.f;
        for (int i = t; i < C2; i += TPB) {
            const float xi = cand2[i].x;
            float above = Ab, eq = 0.f;
            for (int j = 0; j < C2; j++) {
                float2 cj = cand2[j];             // broadcast LDS.64
                if (cj.x > xi) above += cj.y;
                else if (cj.x == xi) eq += cj.y;
            }
            if (above <= target && xi < bx) { bx = xi; bm = above + eq; }
        }
        for (int o = 16; o; o >>= 1) {
            float ox = __shfl_xor_sync(0xffffffffu, bx, o);
            float om = __shfl_xor_sync(0xffffffffu, bm, o);
            if (ox < bx) { bx = ox; bm = om; }
        }
        if (lane == 0) { s_red[warp] = bx; s_rm[warp] = bm; }
        __syncthreads();
        if (t == 0) {
            float fx = s_red[0], fm = s_rm[0];
            #pragma unroll
            for (int i = 1; i < 8; i++)
                if (s_red[i] < fx) { fx = s_red[i]; fm = s_rm[i]; }
            s_fx = fx; s_fm = fm;
        }
        __syncthreads();
        xThr = s_fx; keptMass = s_fm;
    } else {
        // ---- fallback: exact radix select on fkey(x) (R6-proven; never hit) ----
        float (*s_binsW)[256] = reinterpret_cast<float (*)[256]>(s_pool);
        unsigned hi = 0;
        float G = 0.f;
        float km = Z;
        #pragma unroll 1
        for (int pass = 3; pass >= 0; pass--) {
            __syncthreads();
            float4 z4 = make_float4(0.f, 0.f, 0.f, 0.f);
            float4* b4 = reinterpret_cast<float4*>(&s_binsW[0][0]);
            b4[t] = z4; b4[t + TPB] = z4;
            if (t == 0) { s_flag = 0; s_fb = -1; s_digit = 0; s_G2 = 0.f; s_GB = 0.f; }
            __syncthreads();

            const int sh = pass * 8;
            #pragma unroll
            for (int j = 0; j < 4 * NITER; j++) {
                unsigned kk = fkey(x[j]);
                bool cnd = (pass == 3) ? true : ((kk >> (sh + 8)) == hi);
                if (cnd)
                    atomicAdd(&s_binsW[warp][(kk >> sh) & 255u], e[j]);
            }
            __syncthreads();

            const int dgf = 255 - t;
            float vf = 0.f;
            #pragma unroll
            for (int w = 0; w < 8; w++) vf += s_binsW[w][dgf];

            float ivf = vf;
            #pragma unroll
            for (int o = 1; o < 32; o <<= 1) {
                float n = __shfl_up_sync(0xffffffffu, ivf, o);
                if (lane >= o) ivf += n;
            }
            if (lane == 31) s_red[warp] = ivf;
            __syncthreads();
            float wof = 0.f;
            #pragma unroll
            for (int w = 0; w < 8; w++) if (w < warp) wof += s_red[w];
            const float inclf = wof + ivf;
            const float upf = __shfl_up_sync(0xffffffffu, inclf, 1);
            const float prevf = (lane == 0) ? wof : upf;

            const float tgt = target - G;
            if (inclf > tgt && prevf <= tgt) {
                s_digit = dgf; s_G2 = prevf; s_GB = prevf + vf; s_flag = 1;
            }
            __syncthreads();
            if (s_flag == 0 && vf > 0.f) atomicMax(&s_fb, t);
            __syncthreads();
            if (s_flag == 0 && t == s_fb) {
                s_digit = dgf; s_G2 = prevf; s_GB = prevf + vf;
            }
            __syncthreads();

            if (pass == 0) km = G + s_GB;
            G  = G + s_G2;
            hi = (hi << 8) | (unsigned)s_digit;
        }
        xThr = unkey(hi);
        keptMass = km;
    }

    const float rinv = 1.0f / fmaxf(keptMass, 1e-30f);

    // ---- write probs (kept: x >= xThr) ----
    #pragma unroll
    for (int k = 0; k < NITER; k++) {
        int i4 = k * TPB + t;
        if (i4 < NV4) {
            float4 o;
            o.x = (x[4*k+0] >= xThr) ? e[4*k+0] * rinv : 0.f;
            o.y = (x[4*k+1] >= xThr) ? e[4*k+1] * rinv : 0.f;
            o.z = (x[4*k+2] >= xThr) ? e[4*k+2] * rinv : 0.f;
            o.w = (x[4*k+3] >= xThr) ? e[4*k+3] * rinv : 0.f;
            __stcs(&pr4[i4], o);
        }
    }

    // ---- Gumbel-max argmax over kept set (u loaded only where needed) ----
    float best = NEG_INF;
    int   bidx = 0x7fffffff;
    #pragma unroll
    for (int k = 0; k < NITER; k++) {
        int i4 = k * TPB + t;
        if (i4 < NV4) {
            bool k0 = (x[4*k+0] >= xThr);
            bool k1 = (x[4*k+1] >= xThr);
            bool k2 = (x[4*k+2] >= xThr);
            bool k3 = (x[4*k+3] >= xThr);
            if (k0 | k1 | k2 | k3) {
                float4 uu = __ldcs(&u4[i4]);
                float uv[4] = {uu.x, uu.y, uu.z, uu.w};
                bool kk[4] = {k0, k1, k2, k3};
                int base = i4 * 4;
                #pragma unroll
                for (int ci = 0; ci < 4; ci++) {
                    if (kk[ci]) {
                        float g = -logf(-logf(uv[ci]));   // precise, kept-only
                        float val = x[4*k+ci] + g;
                        int idx = base + ci;
                        if (val > best || (val == best && idx < bidx)) {
                            best = val; bidx = idx;
                        }
                    }
                }
            }
        }
    }
    for (int o = 16; o; o >>= 1) {
        float v2 = __shfl_xor_sync(0xffffffffu, best, o);
        int   i2 = __shfl_xor_sync(0xffffffffu, bidx, o);
        if (v2 > best || (v2 == best && i2 < bidx)) { best = v2; bidx = i2; }
    }
    if (lane == 0) { s_red[warp] = best; s_wi[warp] = bidx; }
    __syncthreads();
    if (t == 0) {
        float bb = s_red[0]; int bi = s_wi[0];
        #pragma unroll
        for (int i = 1; i < 8; i++) {
            float v2 = s_red[i]; int i2 = s_wi[i];
            if (v2 > bb || (v2 == bb && i2 < bi)) { bb = v2; bi = i2; }
        }
        out_samp[row] = (float)bi;
    }
}

extern "C" void kernel_launch(void* const* d_in, const int* in_sizes, int n_in,
                              void* d_out, int out_size) {
    const float* logits = (const float*)d_in[0];
    const float* u      = (const float*)d_in[1];
    float* out = (float*)d_out;

    int total = in_sizes[0];
    int B = out_size - total;
    int V;
    if (B > 0 && total % B == 0) {
        V = total / B;
    } else {
        V = 2048;
        B = total / V;
    }
    int NV4 = V / 4;
    int nIter = (NV4 + TPB - 1) / TPB;

    if (nIter <= 1)      sampler_kernel<1><<<B, TPB>>>(logits, u, out, out + B, NV4);
    else if (nIter <= 2) sampler_kernel<2><<<B, TPB>>>(logits, u, out, out + B, NV4);
    else if (nIter <= 4) sampler_kernel<4><<<B, TPB>>>(logits, u, out, out + B, NV4);
    else                 sampler_kernel<8><<<B, TPB>>>(logits, u, out, out + B, NV4);
}

// round 9
// speedup vs baseline: 10.1519x; 1.1601x over previous
#include <cuda_runtime.h>

#define TPB 256

// Bijective, order-preserving float -> uint key (and inverse) — fallback only.
__device__ __forceinline__ unsigned fkey(float f) {
    unsigned u = __float_as_uint(f);
    return u ^ ((unsigned)((int)u >> 31) | 0x80000000u);
}
__device__ __forceinline__ float unkey(unsigned k) {
    unsigned u = (k & 0x80000000u) ? (k ^ 0x80000000u) : ~k;
    return __uint_as_float(u);
}

template<int NITER>
__global__ __launch_bounds__(TPB, 4)
void sampler_kernel(const float* __restrict__ logits,
                    const float* __restrict__ uin,
                    float* __restrict__ out_samp,
                    float* __restrict__ out_probs,
                    int NV4)
{
    // common path: hist = s_pool[0..255]; cand2 = (float2*)(s_pool+512) cap 256
    // fallback path: 8 x 256 per-warp radix bins
    __shared__ float s_pool[2048];
    __shared__ float s_redM[8], s_redZ[8], s_redS[8], s_rm[8];
    __shared__ int   s_wi[8];
    __shared__ int   s_cnt, s_flag, s_fb, s_digit;
    __shared__ float s_G2, s_GB;

    const int row  = blockIdx.x;
    const int t    = threadIdx.x;
    const int lane = t & 31;
    const int warp = t >> 5;
    const float NEG_INF = __int_as_float(0xff800000);

    const float4* lg4 = reinterpret_cast<const float4*>(logits) + (size_t)row * NV4;
    const float4* u4  = reinterpret_cast<const float4*>(uin)    + (size_t)row * NV4;
    float4*       pr4 = reinterpret_cast<float4*>(out_probs)    + (size_t)row * NV4;

    // ---------- Phase A: load, x = logit * 1.25f (== /0.8, proven-equal), max ----------
    float x[4 * NITER];
    float m = NEG_INF;
    #pragma unroll
    for (int k = 0; k < NITER; k++) {
        int i4 = k * TPB + t;
        float4 v = (i4 < NV4) ? __ldcs(&lg4[i4])
                              : make_float4(NEG_INF, NEG_INF, NEG_INF, NEG_INF);
        x[4*k+0] = v.x * 1.25f;
        x[4*k+1] = v.y * 1.25f;
        x[4*k+2] = v.z * 1.25f;
        x[4*k+3] = v.w * 1.25f;
        m = fmaxf(m, fmaxf(fmaxf(x[4*k+0], x[4*k+1]), fmaxf(x[4*k+2], x[4*k+3])));
    }
    for (int o = 16; o; o >>= 1) m = fmaxf(m, __shfl_xor_sync(0xffffffffu, m, o));
    if (lane == 0) s_redM[warp] = m;
    s_pool[t] = 0.f;                                   // zero histogram
    if (t == 0) { s_cnt = 0; s_flag = 0; s_fb = -1; }
    __syncthreads();
    {   // every thread folds the 8 warp maxima itself (no extra barrier)
        float mm = s_redM[0];
        #pragma unroll
        for (int i = 1; i < 8; i++) mm = fmaxf(mm, s_redM[i]);
        m = mm;
    }

    // ---------- Phase B: e = expf(x-m) [precise], Z partial, histogram ----------
    const int   V = NV4 * 4;
    const float W = __logf(20.0f * (float)V) + 0.05f;  // fixed prune window, valid all Z>=1
    const float cutoff = m - W;
    const float bsc = 256.0f / W;

    float* hist = s_pool;
    float e[4 * NITER];
    float zs = 0.f;
    #pragma unroll
    for (int j = 0; j < 4 * NITER; j++) {
        e[j] = expf(x[j] - m);                          // 0 for -inf padding
        zs += e[j];
        if (x[j] >= cutoff) {
            int b = (int)((x[j] - cutoff) * bsc);
            b = (b > 255) ? 255 : b;
            atomicAdd(&hist[b], e[j]);
        }
    }
    for (int o = 16; o; o >>= 1) zs += __shfl_xor_sync(0xffffffffu, zs, o);
    if (lane == 0) s_redZ[warp] = zs;
    __syncthreads();
    float Z = s_redZ[0];
    #pragma unroll
    for (int i = 1; i < 8; i++) Z += s_redZ[i];
    const float target = 0.95f * Z;

    // ---------- Phase C: descending scan of hist, find crossing bin ----------
    const int dg = 255 - t;
    const float v = hist[dg];
    float iv = v;
    #pragma unroll
    for (int o = 1; o < 32; o <<= 1) {
        float n = __shfl_up_sync(0xffffffffu, iv, o);
        if (lane >= o) iv += n;
    }
    if (lane == 31) s_redS[warp] = iv;
    __syncthreads();
    float woff = 0.f;
    #pragma unroll
    for (int w = 0; w < 8; w++) if (w < warp) woff += s_redS[w];
    const float incl = woff + iv;
    const float up = __shfl_up_sync(0xffffffffu, incl, 1);
    const float prev = (lane == 0) ? woff : up;

    if (incl > target && prev <= target) {              // unique crossing thread
        s_digit = dg; s_G2 = prev; s_flag = 1;
    }
    __syncthreads();
    if (s_flag == 0) {                                  // FP-noise fallback (never hit)
        if (v > 0.f) atomicMax(&s_fb, t);
        __syncthreads();
        if (t == s_fb) { s_digit = dg; s_G2 = prev; }
        __syncthreads();
    }
    const int   bstar = s_digit;
    const float Ab    = s_G2;                           // exact mass of bins above b*

    // ---------- Phase D: gather bin-b* candidates (tiny set) ----------
    float2* cand2 = reinterpret_cast<float2*>(s_pool + 512);
    #pragma unroll
    for (int j = 0; j < 4 * NITER; j++) {
        if (x[j] >= cutoff) {
            int b = (int)((x[j] - cutoff) * bsc);
            b = (b > 255) ? 255 : b;
            if (b == bstar) {
                int p = atomicAdd(&s_cnt, 1);
                if (p < 256) cand2[p] = make_float2(x[j], e[j]);
            }
        }
    }
    __syncthreads();
    const int C2 = s_cnt;

    float xThr, keptMass;

    if (C2 <= 256) {
        // ---------- Phase E: exact all-pairs threshold within bin b* ----------
        float bx = 3.4e38f, bm = 0.f;
        for (int i = t; i < C2; i += TPB) {
            const float xi = cand2[i].x;
            float above = Ab, eq = 0.f;
            for (int j = 0; j < C2; j++) {
                float2 cj = cand2[j];                   // broadcast LDS.64
                if (cj.x > xi) above += cj.y;
                else if (cj.x == xi) eq += cj.y;
            }
            if (above <= target && xi < bx) { bx = xi; bm = above + eq; }
        }
        for (int o = 16; o; o >>= 1) {
            float ox = __shfl_xor_sync(0xffffffffu, bx, o);
            float om = __shfl_xor_sync(0xffffffffu, bm, o);
            if (ox < bx) { bx = ox; bm = om; }
        }
        if (lane == 0) { s_redS[warp] = bx; s_rm[warp] = bm; }
        __syncthreads();
        float fx = s_redS[0], fm = s_rm[0];
        #pragma unroll
        for (int i = 1; i < 8; i++)
            if (s_redS[i] < fx) { fx = s_redS[i]; fm = s_rm[i]; }
        xThr = fx; keptMass = fm;
    } else {
        // ---------- fallback: exact radix select on fkey(x) (R6-proven; never hit) ----------
        float (*s_binsW)[256] = reinterpret_cast<float (*)[256]>(s_pool);
        unsigned hi = 0;
        float G = 0.f;
        float km = Z;
        #pragma unroll 1
        for (int pass = 3; pass >= 0; pass--) {
            __syncthreads();
            float4 z4 = make_float4(0.f, 0.f, 0.f, 0.f);
            float4* b4 = reinterpret_cast<float4*>(&s_binsW[0][0]);
            b4[t] = z4; b4[t + TPB] = z4;
            if (t == 0) { s_flag = 0; s_fb = -1; s_digit = 0; s_G2 = 0.f; s_GB = 0.f; }
            __syncthreads();

            const int sh = pass * 8;
            #pragma unroll
            for (int j = 0; j < 4 * NITER; j++) {
                unsigned kk = fkey(x[j]);
                bool cnd = (pass == 3) ? true : ((kk >> (sh + 8)) == hi);
                if (cnd)
                    atomicAdd(&s_binsW[warp][(kk >> sh) & 255u], e[j]);
            }
            __syncthreads();

            const int dgf = 255 - t;
            float vf = 0.f;
            #pragma unroll
            for (int w = 0; w < 8; w++) vf += s_binsW[w][dgf];

            float ivf = vf;
            #pragma unroll
            for (int o = 1; o < 32; o <<= 1) {
                float n = __shfl_up_sync(0xffffffffu, ivf, o);
                if (lane >= o) ivf += n;
            }
            if (lane == 31) s_redS[warp] = ivf;
            __syncthreads();
            float wof = 0.f;
            #pragma unroll
            for (int w = 0; w < 8; w++) if (w < warp) wof += s_redS[w];
            const float inclf = wof + ivf;
            const float upf = __shfl_up_sync(0xffffffffu, inclf, 1);
            const float prevf = (lane == 0) ? wof : upf;

            const float tgt = target - G;
            if (inclf > tgt && prevf <= tgt) {
                s_digit = dgf; s_G2 = prevf; s_GB = prevf + vf; s_flag = 1;
            }
            __syncthreads();
            if (s_flag == 0 && vf > 0.f) atomicMax(&s_fb, t);
            __syncthreads();
            if (s_flag == 0 && t == s_fb) {
                s_digit = dgf; s_G2 = prevf; s_GB = prevf + vf;
            }
            __syncthreads();

            if (pass == 0) km = G + s_GB;
            G  = G + s_G2;
            hi = (hi << 8) | (unsigned)s_digit;
        }
        xThr = unkey(hi);
        keptMass = km;
    }

    const float rinv = 1.0f / fmaxf(keptMass, 1e-30f);

    // ---------- Phase F: write probs (kept: x >= xThr) ----------
    #pragma unroll
    for (int k = 0; k < NITER; k++) {
        int i4 = k * TPB + t;
        if (i4 < NV4) {
            float4 o;
            o.x = (x[4*k+0] >= xThr) ? e[4*k+0] * rinv : 0.f;
            o.y = (x[4*k+1] >= xThr) ? e[4*k+1] * rinv : 0.f;
            o.z = (x[4*k+2] >= xThr) ? e[4*k+2] * rinv : 0.f;
            o.w = (x[4*k+3] >= xThr) ? e[4*k+3] * rinv : 0.f;
            __stcs(&pr4[i4], o);
        }
    }

    // ---------- Gumbel-max argmax over kept set (u loaded only where needed) ----------
    float best = NEG_INF;
    int   bidx = 0x7fffffff;
    #pragma unroll
    for (int k = 0; k < NITER; k++) {
        int i4 = k * TPB + t;
        if (i4 < NV4) {
            bool k0 = (x[4*k+0] >= xThr);
            bool k1 = (x[4*k+1] >= xThr);
            bool k2 = (x[4*k+2] >= xThr);
            bool k3 = (x[4*k+3] >= xThr);
            if (k0 | k1 | k2 | k3) {
                float4 uu = __ldcs(&u4[i4]);
                float uv[4] = {uu.x, uu.y, uu.z, uu.w};
                bool kk[4] = {k0, k1, k2, k3};
                int base = i4 * 4;
                #pragma unroll
                for (int ci = 0; ci < 4; ci++) {
                    if (kk[ci]) {
                        float g = -logf(-logf(uv[ci]));   // precise, kept-only
                        float val = x[4*k+ci] + g;
                        int idx = base + ci;
                        if (val > best || (val == best && idx < bidx)) {
                            best = val; bidx = idx;
                        }
                    }
                }
            }
        }
    }
    for (int o = 16; o; o >>= 1) {
        float v2 = __shfl_xor_sync(0xffffffffu, best, o);
        int   i2 = __shfl_xor_sync(0xffffffffu, bidx, o);
        if (v2 > best || (v2 == best && i2 < bidx)) { best = v2; bidx = i2; }
    }
    if (lane == 0) { s_redM[warp] = best; s_wi[warp] = bidx; }
    __syncthreads();
    if (t == 0) {
        float bb = s_redM[0]; int bi = s_wi[0];
        #pragma unroll
        for (int i = 1; i < 8; i++) {
            float v2 = s_redM[i]; int i2 = s_wi[i];
            if (v2 > bb || (v2 == bb && i2 < bi)) { bb = v2; bi = i2; }
        }
        out_samp[row] = (float)bi;
    }
}

extern "C" void kernel_launch(void* const* d_in, const int* in_sizes, int n_in,
                              void* d_out, int out_size) {
    const float* logits = (const float*)d_in[0];
    const float* u      = (const float*)d_in[1];
    float* out = (float*)d_out;

    int total = in_sizes[0];
    int B = out_size - total;
    int V;
    if (B > 0 && total % B == 0) {
        V = total / B;
    } else {
        V = 2048;
        B = total / V;
    }
    int NV4 = V / 4;
    int nIter = (NV4 + TPB - 1) / TPB;

    if (nIter <= 1)      sampler_kernel<1><<<B, TPB>>>(logits, u, out, out + B, NV4);
    else if (nIter <= 2) sampler_kernel<2><<<B, TPB>>>(logits, u, out, out + B, NV4);
    else if (nIter <= 4) sampler_kernel<4><<<B, TPB>>>(logits, u, out, out + B, NV4);
    else                 sampler_kernel<8><<<B, TPB>>>(logits, u, out, out + B, NV4);
}

// round 10
// speedup vs baseline: 10.6151x; 1.0456x over previous
#include <cuda_runtime.h>

#define TPB 256
#define CANDCAP 1024
#define C2CAP 128

// Bijective, order-preserving float -> uint key (and inverse) — fallback only.
__device__ __forceinline__ unsigned fkey(float f) {
    unsigned u = __float_as_uint(f);
    return u ^ ((unsigned)((int)u >> 31) | 0x80000000u);
}
__device__ __forceinline__ float unkey(unsigned k) {
    unsigned u = (k & 0x80000000u) ? (k ^ 0x80000000u) : ~k;
    return __uint_as_float(u);
}

template<int NITER>
__global__ __launch_bounds__(TPB, 4)
void sampler_kernel(const float* __restrict__ logits,
                    const float* __restrict__ uin,
                    float* __restrict__ out_samp,
                    float* __restrict__ out_probs,
                    int NV4)
{
    // layout: hist[0,256) | s_cx[256,1280) | s_ce[1280,2304) | s_cidx[2304,3328) | cand2[3328,3584)
    // fallback 8x256 radix bins overlay [256,2304)
    __shared__ float s_pool[3584];
    __shared__ float s_redM[8], s_redZ[8], s_redS[8], s_rm[8];
    __shared__ int   s_wi[8], s_wcnt[8];
    __shared__ int   s_cnt2, s_flag, s_fb, s_digit;
    __shared__ float s_G2, s_GB;

    float* hist   = s_pool;
    float* s_cx   = s_pool + 256;
    float* s_ce   = s_pool + 1280;
    int*   s_cidx = reinterpret_cast<int*>(s_pool + 2304);
    float2* cand2 = reinterpret_cast<float2*>(s_pool + 3328);

    const int row  = blockIdx.x;
    const int t    = threadIdx.x;
    const int lane = t & 31;
    const int warp = t >> 5;
    const float NEG_INF = __int_as_float(0xff800000);
    const int   V = NV4 * 4;

    const float4* lg4 = reinterpret_cast<const float4*>(logits) + (size_t)row * NV4;
    const float4* u4  = reinterpret_cast<const float4*>(uin)    + (size_t)row * NV4;
    const float*  urow = uin + (size_t)row * (size_t)V;
    float4*       pr4 = reinterpret_cast<float4*>(out_probs)    + (size_t)row * NV4;

    // ---------- A: load, x = logit * 1.25f (== /0.8, proven-equal), block max ----------
    float x[4 * NITER];
    float m = NEG_INF;
    #pragma unroll
    for (int k = 0; k < NITER; k++) {
        int i4 = k * TPB + t;
        float4 v = (i4 < NV4) ? __ldcs(&lg4[i4])
                              : make_float4(NEG_INF, NEG_INF, NEG_INF, NEG_INF);
        x[4*k+0] = v.x * 1.25f;
        x[4*k+1] = v.y * 1.25f;
        x[4*k+2] = v.z * 1.25f;
        x[4*k+3] = v.w * 1.25f;
        m = fmaxf(m, fmaxf(fmaxf(x[4*k+0], x[4*k+1]), fmaxf(x[4*k+2], x[4*k+3])));
    }
    for (int o = 16; o; o >>= 1) m = fmaxf(m, __shfl_xor_sync(0xffffffffu, m, o));
    if (lane == 0) s_redM[warp] = m;
    s_pool[t] = 0.f;                                  // zero histogram
    if (t == 0) { s_cnt2 = 0; s_flag = 0; s_fb = -1; }
    __syncthreads();                                  // (1)
    {
        float mm = s_redM[0];
        #pragma unroll
        for (int i = 1; i < 8; i++) mm = fmaxf(mm, s_redM[i]);
        m = mm;
    }

    // ---------- B: cheap exp for all; count candidates per warp (ballot) ----------
    const float W = __logf(20.0f * (float)V) + 0.05f; // prune window, valid all Z>=1
    const float cutoff = m - W;
    const float bsc = 256.0f / W;

    float e[4 * NITER];                               // cheap masses (probs values, Z_noncand)
    float zs = 0.f;                                   // non-candidate Z part (cheap ok: <5% mass)
    int wcnt = 0;
    #pragma unroll
    for (int j = 0; j < 4 * NITER; j++) {
        e[j] = __expf(x[j] - m);                      // 0 for -inf padding
        bool pred = (x[j] >= cutoff);
        if (!pred) zs += e[j];
        wcnt += __popc(__ballot_sync(0xffffffffu, pred));
    }
    if (lane == 0) s_wcnt[warp] = wcnt;
    __syncthreads();                                  // (2)
    int wbase = 0, C = 0;
    #pragma unroll
    for (int w = 0; w < 8; w++) { if (w < warp) wbase += s_wcnt[w]; C += s_wcnt[w]; }

    bool fb = (C > CANDCAP);
    float xThr = NEG_INF, keptMass = 1.f, Z = 0.f, target = 0.f;

    if (!fb) {
        // ---------- gather candidates (x, idx) compacted, atomic-free ----------
        int off = 0;
        #pragma unroll
        for (int k = 0; k < NITER; k++) {
            #pragma unroll
            for (int ci = 0; ci < 4; ci++) {
                int j = 4*k + ci;
                bool pred = (x[j] >= cutoff);
                unsigned bal = __ballot_sync(0xffffffffu, pred);
                if (pred) {
                    int p = wbase + off + __popc(bal & ((1u << lane) - 1u));
                    s_cx[p]   = x[j];
                    s_cidx[p] = (k * TPB + t) * 4 + ci;
                }
                off += __popc(bal);
            }
        }
        __syncthreads();                              // (3)

        // ---------- B2: precise exp over compacted candidates; hist; Z ----------
        float zp = 0.f;
        for (int i = t; i < C; i += TPB) {
            float xi = s_cx[i];
            float ei = expf(xi - m);                  // PRECISE: enters mass comparisons
            s_ce[i] = ei;
            int b = (int)((xi - cutoff) * bsc);
            b = (b > 255) ? 255 : b;
            atomicAdd(&hist[b], ei);
            zp += ei;
        }
        float zt = zs + zp;
        for (int o = 16; o; o >>= 1) zt += __shfl_xor_sync(0xffffffffu, zt, o);
        if (lane == 0) s_redZ[warp] = zt;
        __syncthreads();                              // (4)
        Z = s_redZ[0];
        #pragma unroll
        for (int i = 1; i < 8; i++) Z += s_redZ[i];
        target = 0.95f * Z;

        // ---------- C: descending scan of hist, crossing bin ----------
        const int dg = 255 - t;
        const float v = hist[dg];
        float iv = v;
        #pragma unroll
        for (int o = 1; o < 32; o <<= 1) {
            float n = __shfl_up_sync(0xffffffffu, iv, o);
            if (lane >= o) iv += n;
        }
        if (lane == 31) s_redS[warp] = iv;
        __syncthreads();                              // (5)
        float woff = 0.f;
        #pragma unroll
        for (int w = 0; w < 8; w++) if (w < warp) woff += s_redS[w];
        const float incl = woff + iv;
        const float up = __shfl_up_sync(0xffffffffu, incl, 1);
        const float prev = (lane == 0) ? woff : up;

        if (incl > target && prev <= target) { s_digit = dg; s_G2 = prev; s_flag = 1; }
        __syncthreads();                              // (6)
        if (s_flag == 0) {                            // FP-noise fallback (never hit)
            if (v > 0.f) atomicMax(&s_fb, t);
            __syncthreads();
            if (t == s_fb) { s_digit = dg; s_G2 = prev; }
            __syncthreads();
        }
        const int   bstar = s_digit;
        const float Ab    = s_G2;

        // ---------- D: gather bin-b* candidates (tiny) ----------
        for (int i = t; i < C; i += TPB) {
            float xi = s_cx[i];
            int b = (int)((xi - cutoff) * bsc);
            b = (b > 255) ? 255 : b;
            if (b == bstar) {
                int p = atomicAdd(&s_cnt2, 1);
                if (p < C2CAP) cand2[p] = make_float2(xi, s_ce[i]);
            }
        }
        __syncthreads();                              // (7)
        const int C2 = s_cnt2;

        if (C2 <= C2CAP) {
            // ---------- E: exact all-pairs threshold within bin b* ----------
            float bx = 3.4e38f, bm = 0.f;
            for (int i = t; i < C2; i += TPB) {
                const float xi = cand2[i].x;
                float above = Ab, eq = 0.f;
                for (int j = 0; j < C2; j++) {
                    float2 cj = cand2[j];             // broadcast LDS.64
                    if (cj.x > xi) above += cj.y;
                    else if (cj.x == xi) eq += cj.y;
                }
                if (above <= target && xi < bx) { bx = xi; bm = above + eq; }
            }
            for (int o = 16; o; o >>= 1) {
                float ox = __shfl_xor_sync(0xffffffffu, bx, o);
                float om = __shfl_xor_sync(0xffffffffu, bm, o);
                if (ox < bx) { bx = ox; bm = om; }
            }
            if (lane == 0) { s_redS[warp] = bx; s_rm[warp] = bm; }
            __syncthreads();                          // (8)
            float fx = s_redS[0], fm = s_rm[0];
            #pragma unroll
            for (int i = 1; i < 8; i++)
                if (s_redS[i] < fx) { fx = s_redS[i]; fm = s_rm[i]; }
            xThr = fx; keptMass = fm;
        } else fb = true;
    }

    if (fb) {
        // ---------- fallback: exact radix select on fkey(x) (R6-proven; never hit) ----------
        // Z from register (cheap) masses — acceptable for this unreachable path.
        float zf = 0.f;
        #pragma unroll
        for (int j = 0; j < 4 * NITER; j++) zf += e[j];
        for (int o = 16; o; o >>= 1) zf += __shfl_xor_sync(0xffffffffu, zf, o);
        __syncthreads();
        if (lane == 0) s_redZ[warp] = zf;
        __syncthreads();
        Z = s_redZ[0];
        #pragma unroll
        for (int i = 1; i < 8; i++) Z += s_redZ[i];
        target = 0.95f * Z;

        float (*s_binsW)[256] = reinterpret_cast<float (*)[256]>(s_pool + 256);
        unsigned hi = 0;
        float G = 0.f;
        float km = Z;
        #pragma unroll 1
        for (int pass = 3; pass >= 0; pass--) {
            __syncthreads();
            float4 z4 = make_float4(0.f, 0.f, 0.f, 0.f);
            float4* b4 = reinterpret_cast<float4*>(&s_binsW[0][0]);
            b4[t] = z4; b4[t + TPB] = z4;
            if (t == 0) { s_flag = 0; s_fb = -1; s_digit = 0; s_G2 = 0.f; s_GB = 0.f; }
            __syncthreads();

            const int sh = pass * 8;
            #pragma unroll
            for (int j = 0; j < 4 * NITER; j++) {
                unsigned kk = fkey(x[j]);
                bool cnd = (pass == 3) ? true : ((kk >> (sh + 8)) == hi);
                if (cnd) atomicAdd(&s_binsW[warp][(kk >> sh) & 255u], e[j]);
            }
            __syncthreads();

            const int dgf = 255 - t;
            float vf = 0.f;
            #pragma unroll
            for (int w = 0; w < 8; w++) vf += s_binsW[w][dgf];

            float ivf = vf;
            #pragma unroll
            for (int o = 1; o < 32; o <<= 1) {
                float n = __shfl_up_sync(0xffffffffu, ivf, o);
                if (lane >= o) ivf += n;
            }
            if (lane == 31) s_redS[warp] = ivf;
            __syncthreads();
            float wof = 0.f;
            #pragma unroll
            for (int w = 0; w < 8; w++) if (w < warp) wof += s_redS[w];
            const float inclf = wof + ivf;
            const float upf = __shfl_up_sync(0xffffffffu, inclf, 1);
            const float prevf = (lane == 0) ? wof : upf;

            const float tgt = target - G;
            if (inclf > tgt && prevf <= tgt) {
                s_digit = dgf; s_G2 = prevf; s_GB = prevf + vf; s_flag = 1;
            }
            __syncthreads();
            if (s_flag == 0 && vf > 0.f) atomicMax(&s_fb, t);
            __syncthreads();
            if (s_flag == 0 && t == s_fb) {
                s_digit = dgf; s_G2 = prevf; s_GB = prevf + vf;
            }
            __syncthreads();

            if (pass == 0) km = G + s_GB;
            G  = G + s_G2;
            hi = (hi << 8) | (unsigned)s_digit;
        }
        xThr = unkey(hi);
        keptMass = km;
    }

    const float rinv = 1.0f / fmaxf(keptMass, 1e-30f);

    // ---------- F: write probs (kept: x >= xThr); values cheap-exp (tol 1e-3) ----------
    #pragma unroll
    for (int k = 0; k < NITER; k++) {
        int i4 = k * TPB + t;
        if (i4 < NV4) {
            float4 o;
            o.x = (x[4*k+0] >= xThr) ? e[4*k+0] * rinv : 0.f;
            o.y = (x[4*k+1] >= xThr) ? e[4*k+1] * rinv : 0.f;
            o.z = (x[4*k+2] >= xThr) ? e[4*k+2] * rinv : 0.f;
            o.w = (x[4*k+3] >= xThr) ? e[4*k+3] * rinv : 0.f;
            __stcs(&pr4[i4], o);
        }
    }

    // ---------- G: Gumbel-max argmax over kept set ----------
    float best = NEG_INF;
    int   bidx = 0x7fffffff;
    if (!fb) {
        // compacted: kept subset of candidates; scattered u loads, kept-only logs
        for (int i = t; i < C; i += TPB) {
            float xi = s_cx[i];
            if (xi >= xThr) {
                int idx = s_cidx[i];
                float uu = __ldcs(&urow[idx]);
                float g = -logf(-logf(uu));           // precise
                float val = xi + g;
                if (val > best || (val == best && idx < bidx)) { best = val; bidx = idx; }
            }
        }
    } else {
        #pragma unroll
        for (int k = 0; k < NITER; k++) {
            int i4 = k * TPB + t;
            if (i4 < NV4) {
                bool k0 = (x[4*k+0] >= xThr), k1 = (x[4*k+1] >= xThr);
                bool k2 = (x[4*k+2] >= xThr), k3 = (x[4*k+3] >= xThr);
                if (k0 | k1 | k2 | k3) {
                    float4 uu = __ldcs(&u4[i4]);
                    float uv[4] = {uu.x, uu.y, uu.z, uu.w};
                    bool kk[4] = {k0, k1, k2, k3};
                    int base = i4 * 4;
                    #pragma unroll
                    for (int ci = 0; ci < 4; ci++) {
                        if (kk[ci]) {
                            float g = -logf(-logf(uv[ci]));
                            float val = x[4*k+ci] + g;
                            int idx = base + ci;
                            if (val > best || (val == best && idx < bidx)) { best = val; bidx = idx; }
                        }
                    }
                }
            }
        }
    }
    for (int o = 16; o; o >>= 1) {
        float v2 = __shfl_xor_sync(0xffffffffu, best, o);
        int   i2 = __shfl_xor_sync(0xffffffffu, bidx, o);
        if (v2 > best || (v2 == best && i2 < bidx)) { best = v2; bidx = i2; }
    }
    if (lane == 0) { s_redM[warp] = best; s_wi[warp] = bidx; }
    __syncthreads();                                  // (9)
    if (t == 0) {
        float bb = s_redM[0]; int bi = s_wi[0];
        #pragma unroll
        for (int i = 1; i < 8; i++) {
            float v2 = s_redM[i]; int i2 = s_wi[i];
            if (v2 > bb || (v2 == bb && i2 < bi)) { bb = v2; bi = i2; }
        }
        out_samp[row] = (float)bi;
    }
}

extern "C" void kernel_launch(void* const* d_in, const int* in_sizes, int n_in,
                              void* d_out, int out_size) {
    const float* logits = (const float*)d_in[0];
    const float* u      = (const float*)d_in[1];
    float* out = (float*)d_out;

    int total = in_sizes[0];
    int B = out_size - total;
    int V;
    if (B > 0 && total % B == 0) {
        V = total / B;
    } else {
        V = 2048;
        B = total / V;
    }
    int NV4 = V / 4;
    int nIter = (NV4 + TPB - 1) / TPB;

    if (nIter <= 1)      sampler_kernel<1><<<B, TPB>>>(logits, u, out, out + B, NV4);
    else if (nIter <= 2) sampler_kernel<2><<<B, TPB>>>(logits, u, out, out + B, NV4);
    else if (nIter <= 4) sampler_kernel<4><<<B, TPB>>>(logits, u, out, out + B, NV4);
    else                 sampler_kernel<8><<<B, TPB>>>(logits, u, out, out + B, NV4);
}